// round 9
// baseline (speedup 1.0000x reference)
#include <cuda_runtime.h>
#include <cuda_bf16.h>

// ---------------- problem constants ----------------
#define BB 8
#define NN 131072
#define SS 1024
#define KK 64
#define CC 32
#define HH 64          // 2*C
#define D1 38          // C + 6
#define D2 70          // H + 6
#define H3 256         // 4*H

// output layout (flattened concat of the 4 returned tensors)
#define OFF_LOCS  0
#define OFF_OUT   (BB*SS*3)                  // 24576
#define OFF_BOXES (OFF_OUT + BB*HH*SS)       // 548864
#define OFF_INDS  (OFF_BOXES + BB*SS*6)      // 598016

typedef unsigned long long ull;

// ---------------- f32x2 packed helpers (sm_100+) ----------------
__device__ __forceinline__ ull pack2(float lo, float hi) {
    ull r; asm("mov.b64 %0, {%1, %2};" : "=l"(r) : "f"(lo), "f"(hi)); return r;
}
__device__ __forceinline__ void unpack2(ull v, float& lo, float& hi) {
    asm("mov.b64 {%0, %1}, %2;" : "=f"(lo), "=f"(hi) : "l"(v));
}
__device__ __forceinline__ void fma2(ull& d, ull a, ull b) {
    asm("fma.rn.f32x2 %0, %1, %2, %0;" : "+l"(d) : "l"(a), "l"(b));
}

// ---------------- scratch (device globals; no allocation allowed) ----------
__device__ float g_feats_nc[BB * NN * CC];   // [B,N,C] transposed feats
__device__ float g_dimbox  [BB * NN * 3];
__device__ float g_fps_locs[BB * SS * 3];
__device__ float g_fps_dim [BB * SS * 3];
__device__ float g_newfeat [BB * SS * HH];   // stage1 output == identity
__device__ float g_h2max   [BB * SS * HH];   // stage2 output

// ---------------- prep: transpose feats, compute dim boxes ----------------
__global__ __launch_bounds__(256) void prep_kernel(
    const float* __restrict__ feats, const float* __restrict__ boxes)
{
    int idx = blockIdx.x * blockDim.x + threadIdx.x;   // over B*N
    if (idx >= BB * NN) return;
    int b = idx >> 17;
    int n = idx & (NN - 1);

    float tmp[CC];
    #pragma unroll
    for (int c = 0; c < CC; c++)
        tmp[c] = feats[(b * CC + c) * NN + n];

    float4* dst = (float4*)(g_feats_nc + ((size_t)idx << 5));
    #pragma unroll
    for (int q = 0; q < 8; q++)
        dst[q] = make_float4(tmp[4*q], tmp[4*q+1], tmp[4*q+2], tmp[4*q+3]);

    const float* bx = boxes + (size_t)idx * 6;
    float* dd = g_dimbox + (size_t)idx * 3;
    dd[0] = bx[3] - bx[0];
    dd[1] = bx[4] - bx[1];
    dd[2] = bx[5] - bx[2];
}

// ---------------- fps gather ----------
__global__ __launch_bounds__(256) void fps_kernel(
    const float* __restrict__ locs, const float* __restrict__ boxes,
    const int* __restrict__ fps_inds, float* __restrict__ out)
{
    int idx = blockIdx.x * blockDim.x + threadIdx.x;   // over B*S
    if (idx >= BB * SS) return;
    int b = idx >> 10;
    int j = fps_inds[idx];

    const float* lp = locs + ((size_t)b * NN + j) * 3;
    float l0 = lp[0], l1 = lp[1], l2 = lp[2];
    g_fps_locs[idx*3+0] = l0; g_fps_locs[idx*3+1] = l1; g_fps_locs[idx*3+2] = l2;
    out[OFF_LOCS + idx*3 + 0] = l0;
    out[OFF_LOCS + idx*3 + 1] = l1;
    out[OFF_LOCS + idx*3 + 2] = l2;

    const float* bx = boxes + ((size_t)b * NN + j) * 6;
    float b0 = bx[0], b1 = bx[1], b2 = bx[2], b3 = bx[3], b4 = bx[4], b5 = bx[5];
    g_fps_dim[idx*3+0] = b3 - b0;
    g_fps_dim[idx*3+1] = b4 - b1;
    g_fps_dim[idx*3+2] = b5 - b2;
    out[OFF_BOXES + idx*6 + 0] = b0;
    out[OFF_BOXES + idx*6 + 1] = b1;
    out[OFF_BOXES + idx*6 + 2] = b2;
    out[OFF_BOXES + idx*6 + 3] = b3;
    out[OFF_BOXES + idx*6 + 4] = b4;
    out[OFF_BOXES + idx*6 + 5] = b5;

    out[OFF_INDS + idx] = (float)j;
}

// ================= stage 1: 2 queries/block, 128 thr/query ==============
// smem floats: wa[1216] wb[2048] ba[32] bb[64] | per-q: g1[2432] h1[2048]
#define S1_BASE (D1*CC + CC*HH + CC + HH)       // 3360
#define S1_PERQ (D1*64 + CC*64)                 // 4480
#define S1_SMEM ((S1_BASE + 2*S1_PERQ) * 4)     // 49280 bytes

__global__ __launch_bounds__(256, 4) void stage1_kernel(
    const float* __restrict__ locs, const int* __restrict__ nbr,
    const float* __restrict__ w1a, const float* __restrict__ s1a, const float* __restrict__ t1a,
    const float* __restrict__ w1b, const float* __restrict__ s1b, const float* __restrict__ t1b)
{
    extern __shared__ float sm[];
    float* wa_s = sm;                 // D1*CC
    float* wb_s = wa_s + D1*CC;       // CC*HH
    float* ba_s = wb_s + CC*HH;       // CC
    float* bb_s = ba_s + CC;          // HH
    int tid  = threadIdx.x;
    int q    = tid >> 7;              // 0..1
    int ltid = tid & 127;
    float* g1_s = sm + S1_BASE + q * S1_PERQ;   // D1*64
    float* h1_s = g1_s + D1*64;                 // CC*64
    float* red  = g1_s;               // overlay (g1 dead after GEMM A, synced)

    int bs = blockIdx.x * 2 + q;
    int b  = bs >> 10;

    for (int i = tid; i < D1 * CC; i += 256) wa_s[i] = w1a[i] * s1a[i & 31];
    for (int i = tid; i < CC * HH; i += 256) wb_s[i] = w1b[i] * s1b[i & 63];
    if (tid < CC) ba_s[tid] = t1a[tid];
    if (tid < HH) bb_s[tid] = t1b[tid];

    // ---- fill g1_s[i][n]: 2 threads per neighbor ----
    {
        int nb   = ltid & 63;
        int half = ltid >> 6;
        int j = nbr[bs * KK + nb];
        if (half == 0) {
            const float* lp = locs + ((size_t)b * NN + j) * 3;
            g1_s[0*64 + nb] = (lp[0] - g_fps_locs[bs*3+0]) * 2.5f;
            g1_s[1*64 + nb] = (lp[1] - g_fps_locs[bs*3+1]) * 2.5f;
            g1_s[2*64 + nb] = (lp[2] - g_fps_locs[bs*3+2]) * 2.5f;
            const float* dp = g_dimbox + ((size_t)b * NN + j) * 3;
            g1_s[3*64 + nb] = fabsf(dp[0] - g_fps_dim[bs*3+0]);
            g1_s[4*64 + nb] = fabsf(dp[1] - g_fps_dim[bs*3+1]);
            g1_s[5*64 + nb] = fabsf(dp[2] - g_fps_dim[bs*3+2]);
            const float4* fp = (const float4*)(g_feats_nc + (((size_t)b * NN + j) << 5));
            #pragma unroll
            for (int qq = 0; qq < 4; qq++) {
                float4 v = fp[qq];
                g1_s[(6+4*qq+0)*64 + nb] = v.x;
                g1_s[(6+4*qq+1)*64 + nb] = v.y;
                g1_s[(6+4*qq+2)*64 + nb] = v.z;
                g1_s[(6+4*qq+3)*64 + nb] = v.w;
            }
        } else {
            const float4* fp = (const float4*)(g_feats_nc + (((size_t)b * NN + j) << 5));
            #pragma unroll
            for (int qq = 4; qq < 8; qq++) {
                float4 v = fp[qq];
                g1_s[(6+4*qq+0)*64 + nb] = v.x;
                g1_s[(6+4*qq+1)*64 + nb] = v.y;
                g1_s[(6+4*qq+2)*64 + nb] = v.z;
                g1_s[(6+4*qq+3)*64 + nb] = v.w;
            }
        }
    }
    __syncthreads();

    int cgrp = ltid & 7, ngrp = ltid >> 3;   // 8 cgrps x 16 ngrps
    int n0 = ngrp * 4;

    // ---- GEMM A: 38 -> 32, relu. Tile 4n x 4c (2 ch-pairs). ----
    {
        int c0 = cgrp * 4;
        ull acc[4][2];
        ull bi0 = pack2(ba_s[c0+0], ba_s[c0+1]);
        ull bi1 = pack2(ba_s[c0+2], ba_s[c0+3]);
        #pragma unroll
        for (int n = 0; n < 4; n++) { acc[n][0] = bi0; acc[n][1] = bi1; }

        #pragma unroll 2
        for (int i = 0; i < D1; i++) {
            float4 gv = *(const float4*)(g1_s + i * 64 + n0);
            ulonglong2 wv = *(const ulonglong2*)(wa_s + i * CC + c0);
            ull gg[4] = { pack2(gv.x,gv.x), pack2(gv.y,gv.y), pack2(gv.z,gv.z), pack2(gv.w,gv.w) };
            #pragma unroll
            for (int n = 0; n < 4; n++) {
                fma2(acc[n][0], gg[n], wv.x);
                fma2(acc[n][1], gg[n], wv.y);
            }
        }
        // relu + store [c][n] as float4 per channel
        #pragma unroll
        for (int p = 0; p < 2; p++) {
            float lo[4], hi[4];
            #pragma unroll
            for (int n = 0; n < 4; n++) unpack2(acc[n][p], lo[n], hi[n]);
            *(float4*)(h1_s + (c0+2*p+0)*64 + n0) =
                make_float4(fmaxf(lo[0],0.f), fmaxf(lo[1],0.f), fmaxf(lo[2],0.f), fmaxf(lo[3],0.f));
            *(float4*)(h1_s + (c0+2*p+1)*64 + n0) =
                make_float4(fmaxf(hi[0],0.f), fmaxf(hi[1],0.f), fmaxf(hi[2],0.f), fmaxf(hi[3],0.f));
        }
    }
    __syncthreads();

    // ---- GEMM B: 32 -> 64, max over K. Tile 4n x 8c (4 ch-pairs). ----
    float m[8];
    {
        int c0 = cgrp * 8;
        ull acc[4][4];
        #pragma unroll
        for (int p = 0; p < 4; p++) {
            ull bi = pack2(bb_s[c0+2*p], bb_s[c0+2*p+1]);
            #pragma unroll
            for (int n = 0; n < 4; n++) acc[n][p] = bi;
        }
        #pragma unroll 2
        for (int i = 0; i < CC; i++) {
            float4 gv = *(const float4*)(h1_s + i * 64 + n0);
            ulonglong2 w0 = *(const ulonglong2*)(wb_s + i * HH + c0);
            ulonglong2 w1 = *(const ulonglong2*)(wb_s + i * HH + c0 + 4);
            ull wc[4] = { w0.x, w0.y, w1.x, w1.y };
            ull gg[4] = { pack2(gv.x,gv.x), pack2(gv.y,gv.y), pack2(gv.z,gv.z), pack2(gv.w,gv.w) };
            #pragma unroll
            for (int n = 0; n < 4; n++)
                #pragma unroll
                for (int p = 0; p < 4; p++) fma2(acc[n][p], gg[n], wc[p]);
        }
        // local max over 4 neighbors (relu deferred: monotone)
        #pragma unroll
        for (int p = 0; p < 4; p++) {
            float lo, hi; unpack2(acc[0][p], lo, hi);
            m[2*p] = lo; m[2*p+1] = hi;
            #pragma unroll
            for (int n = 1; n < 4; n++) {
                unpack2(acc[n][p], lo, hi);
                m[2*p]   = fmaxf(m[2*p], lo);
                m[2*p+1] = fmaxf(m[2*p+1], hi);
            }
        }
    }
    // warp reduce over 4 ngrps (lanes ^8, ^16)
    #pragma unroll
    for (int cc = 0; cc < 8; cc++) {
        m[cc] = fmaxf(m[cc], __shfl_xor_sync(0xffffffffu, m[cc], 8));
        m[cc] = fmaxf(m[cc], __shfl_xor_sync(0xffffffffu, m[cc], 16));
    }
    __syncthreads();   // before red overlays g1_s
    if ((ltid & 24) == 0) {            // one lane-group per warp
        int w = ltid >> 5;             // warp within query (0..3)
        #pragma unroll
        for (int cc = 0; cc < 8; cc++) red[w * 68 + cgrp * 8 + cc] = m[cc];
    }
    __syncthreads();

    if (ltid < 64) {
        float mm = red[ltid];
        #pragma unroll
        for (int r = 1; r < 4; r++) mm = fmaxf(mm, red[r * 68 + ltid]);
        g_newfeat[bs * HH + ltid] = fmaxf(mm, 0.0f);
    }
}

// ================= stage 2: 2 queries/block, 128 thr/query ==============
// smem floats: w[4480] sb[64] | per-q: g[4480] (red overlaid)
#define S2_BASE (D2*HH + HH)                    // 4544
#define S2_PERQ (D2*64)                         // 4480
#define S2_SMEM ((S2_BASE + 2*S2_PERQ) * 4)     // 54016 bytes

__global__ __launch_bounds__(256, 4) void stage2_kernel(
    const int* __restrict__ nbr2,
    const float* __restrict__ w2, const float* __restrict__ s2, const float* __restrict__ t2)
{
    extern __shared__ float sm[];
    float* w_s = sm;                  // D2*HH
    float* sb  = w_s + D2*HH;         // HH
    int tid  = threadIdx.x;
    int q    = tid >> 7;
    int ltid = tid & 127;
    float* g_s = sm + S2_BASE + q * S2_PERQ;   // D2*64
    float* red = g_s;                 // overlay after compute (synced)

    int bs = blockIdx.x * 2 + q;
    int b  = bs >> 10;

    for (int i = tid; i < D2 * HH; i += 256) w_s[i] = w2[i] * s2[i & 63];
    if (tid < HH) sb[tid] = t2[tid];

    // ---- fill g_s[i][n]: 2 threads per neighbor ----
    {
        int nb   = ltid & 63;
        int half = ltid >> 6;
        int j  = nbr2[bs * KK + nb];
        int fj = (b << 10) + j;
        const float4* fp = (const float4*)(g_newfeat + (size_t)fj * HH);
        if (half == 0) {
            g_s[0*64 + nb] = (g_fps_locs[fj*3+0] - g_fps_locs[bs*3+0]) * 1.25f;
            g_s[1*64 + nb] = (g_fps_locs[fj*3+1] - g_fps_locs[bs*3+1]) * 1.25f;
            g_s[2*64 + nb] = (g_fps_locs[fj*3+2] - g_fps_locs[bs*3+2]) * 1.25f;
            g_s[3*64 + nb] = fabsf(g_fps_dim[fj*3+0] - g_fps_dim[bs*3+0]);
            g_s[4*64 + nb] = fabsf(g_fps_dim[fj*3+1] - g_fps_dim[bs*3+1]);
            g_s[5*64 + nb] = fabsf(g_fps_dim[fj*3+2] - g_fps_dim[bs*3+2]);
            #pragma unroll
            for (int qq = 0; qq < 8; qq++) {
                float4 v = fp[qq];
                g_s[(6+4*qq+0)*64 + nb] = v.x;
                g_s[(6+4*qq+1)*64 + nb] = v.y;
                g_s[(6+4*qq+2)*64 + nb] = v.z;
                g_s[(6+4*qq+3)*64 + nb] = v.w;
            }
        } else {
            #pragma unroll
            for (int qq = 8; qq < 16; qq++) {
                float4 v = fp[qq];
                g_s[(6+4*qq+0)*64 + nb] = v.x;
                g_s[(6+4*qq+1)*64 + nb] = v.y;
                g_s[(6+4*qq+2)*64 + nb] = v.z;
                g_s[(6+4*qq+3)*64 + nb] = v.w;
            }
        }
    }
    __syncthreads();

    int cgrp = ltid & 7, ngrp = ltid >> 3;
    int n0 = ngrp * 4, c0 = cgrp * 8;

    float m[8];
    {
        ull acc[4][4];
        #pragma unroll
        for (int p = 0; p < 4; p++) {
            ull bi = pack2(sb[c0+2*p], sb[c0+2*p+1]);
            #pragma unroll
            for (int n = 0; n < 4; n++) acc[n][p] = bi;
        }
        #pragma unroll 2
        for (int i = 0; i < D2; i++) {
            float4 gv = *(const float4*)(g_s + i * 64 + n0);
            ulonglong2 w0 = *(const ulonglong2*)(w_s + i * HH + c0);
            ulonglong2 w1 = *(const ulonglong2*)(w_s + i * HH + c0 + 4);
            ull wc[4] = { w0.x, w0.y, w1.x, w1.y };
            ull gg[4] = { pack2(gv.x,gv.x), pack2(gv.y,gv.y), pack2(gv.z,gv.z), pack2(gv.w,gv.w) };
            #pragma unroll
            for (int n = 0; n < 4; n++)
                #pragma unroll
                for (int p = 0; p < 4; p++) fma2(acc[n][p], gg[n], wc[p]);
        }
        // local max over 4 neighbors (no relu in stage 2)
        #pragma unroll
        for (int p = 0; p < 4; p++) {
            float lo, hi; unpack2(acc[0][p], lo, hi);
            m[2*p] = lo; m[2*p+1] = hi;
            #pragma unroll
            for (int n = 1; n < 4; n++) {
                unpack2(acc[n][p], lo, hi);
                m[2*p]   = fmaxf(m[2*p], lo);
                m[2*p+1] = fmaxf(m[2*p+1], hi);
            }
        }
    }
    #pragma unroll
    for (int cc = 0; cc < 8; cc++) {
        m[cc] = fmaxf(m[cc], __shfl_xor_sync(0xffffffffu, m[cc], 8));
        m[cc] = fmaxf(m[cc], __shfl_xor_sync(0xffffffffu, m[cc], 16));
    }
    __syncthreads();   // before red overlays g_s
    if ((ltid & 24) == 0) {
        int w = ltid >> 5;
        #pragma unroll
        for (int cc = 0; cc < 8; cc++) red[w * 68 + cgrp * 8 + cc] = m[cc];
    }
    __syncthreads();

    if (ltid < 64) {
        float mm = red[ltid];
        #pragma unroll
        for (int r = 1; r < 4; r++) mm = fmaxf(mm, red[r * 68 + ltid]);
        g_h2max[bs * HH + ltid] = mm;
    }
}

// ---------------- stage 3: bottleneck mlp3 + skip, write transposed ------
#define TS 16
__global__ __launch_bounds__(256) void stage3_kernel(
    const float* __restrict__ w3a, const float* __restrict__ s3a, const float* __restrict__ t3a,
    const float* __restrict__ w3b, const float* __restrict__ s3b, const float* __restrict__ t3b,
    float* __restrict__ out)
{
    __shared__ float h2s[TS * HH];
    __shared__ float h3s[TS * H3];
    int t = threadIdx.x;
    int row0 = blockIdx.x * TS;

    for (int i = t; i < TS * HH; i += 256) h2s[i] = g_h2max[row0 * HH + i];
    __syncthreads();

    {
        float sc = s3a[t], bi = t3a[t];
        float acc[TS];
        #pragma unroll
        for (int r = 0; r < TS; r++) acc[r] = bi;
        #pragma unroll 4
        for (int i = 0; i < HH; i++) {
            float wv = w3a[i * H3 + t] * sc;
            #pragma unroll
            for (int r = 0; r < TS; r++) acc[r] += h2s[r * HH + i] * wv;
        }
        #pragma unroll
        for (int r = 0; r < TS; r++) h3s[r * H3 + t] = fmaxf(acc[r], 0.0f);
    }
    __syncthreads();

    {
        int c  = t & 63;
        int rg = t >> 6;
        float sc = s3b[c], bi = t3b[c];
        float acc[4];
        #pragma unroll
        for (int rr = 0; rr < 4; rr++) acc[rr] = bi;
        #pragma unroll 4
        for (int i = 0; i < H3; i++) {
            float wv = w3b[i * HH + c] * sc;
            #pragma unroll
            for (int rr = 0; rr < 4; rr++)
                acc[rr] += h3s[(rg * 4 + rr) * H3 + i] * wv;
        }
        #pragma unroll
        for (int rr = 0; rr < 4; rr++) {
            int row = row0 + rg * 4 + rr;
            int b = row >> 10, s = row & 1023;
            float v = acc[rr] + g_newfeat[row * HH + c];
            out[OFF_OUT + ((b * HH + c) << 10) + s] = fmaxf(v, 0.0f);
        }
    }
}

// ---------------- launch ----------------
extern "C" void kernel_launch(void* const* d_in, const int* in_sizes, int n_in,
                              void* d_out, int out_size)
{
    const float* locs  = (const float*)d_in[0];
    const float* feats = (const float*)d_in[1];
    const float* boxes = (const float*)d_in[2];
    const int*   fps   = (const int*)d_in[3];
    const int*   nbr   = (const int*)d_in[4];
    const int*   nbr2  = (const int*)d_in[5];
    const float* w1a = (const float*)d_in[6];
    const float* s1a = (const float*)d_in[7];
    const float* t1a = (const float*)d_in[8];
    const float* w1b = (const float*)d_in[9];
    const float* s1b = (const float*)d_in[10];
    const float* t1b = (const float*)d_in[11];
    const float* w2  = (const float*)d_in[12];
    const float* s2  = (const float*)d_in[13];
    const float* t2  = (const float*)d_in[14];
    const float* w3a = (const float*)d_in[15];
    const float* s3a = (const float*)d_in[16];
    const float* t3a = (const float*)d_in[17];
    const float* w3b = (const float*)d_in[18];
    const float* s3b = (const float*)d_in[19];
    const float* t3b = (const float*)d_in[20];
    float* out = (float*)d_out;

    cudaFuncSetAttribute(stage1_kernel, cudaFuncAttributeMaxDynamicSharedMemorySize, S1_SMEM);
    cudaFuncSetAttribute(stage2_kernel, cudaFuncAttributeMaxDynamicSharedMemorySize, S2_SMEM);

    prep_kernel<<<(BB * NN + 255) / 256, 256>>>(feats, boxes);
    fps_kernel<<<(BB * SS + 255) / 256, 256>>>(locs, boxes, fps, out);
    stage1_kernel<<<BB * SS / 2, 256, S1_SMEM>>>(locs, nbr, w1a, s1a, t1a, w1b, s1b, t1b);
    stage2_kernel<<<BB * SS / 2, 256, S2_SMEM>>>(nbr2, w2, s2, t2);
    stage3_kernel<<<(BB * SS) / TS, 256>>>(w3a, s3a, t3a, w3b, s3b, t3b, out);
}

// round 10
// speedup vs baseline: 1.1588x; 1.1588x over previous
#include <cuda_runtime.h>
#include <cuda_bf16.h>

// ---------------- problem constants ----------------
#define BB 8
#define NN 131072
#define SS 1024
#define KK 64
#define CC 32
#define HH 64          // 2*C
#define D1 38          // C + 6
#define D2 70          // H + 6
#define H3 256         // 4*H

#define CH 32          // neighbor chunk size
#define NCHUNK (KK/CH) // 2

// output layout (flattened concat of the 4 returned tensors)
#define OFF_LOCS  0
#define OFF_OUT   (BB*SS*3)                  // 24576
#define OFF_BOXES (OFF_OUT + BB*HH*SS)       // 548864
#define OFF_INDS  (OFF_BOXES + BB*SS*6)      // 598016

typedef unsigned long long ull;

// ---------------- f32x2 packed helpers (sm_100+) ----------------
__device__ __forceinline__ ull pack2(float lo, float hi) {
    ull r; asm("mov.b64 %0, {%1, %2};" : "=l"(r) : "f"(lo), "f"(hi)); return r;
}
__device__ __forceinline__ void unpack2(ull v, float& lo, float& hi) {
    asm("mov.b64 {%0, %1}, %2;" : "=f"(lo), "=f"(hi) : "l"(v));
}
__device__ __forceinline__ void fma2(ull& d, ull a, ull b) {
    asm("fma.rn.f32x2 %0, %1, %2, %0;" : "+l"(d) : "l"(a), "l"(b));
}

// ---------------- scratch (device globals; no allocation allowed) ----------
__device__ float g_feats_nc[BB * NN * CC];   // [B,N,C] transposed feats
__device__ float g_dimbox  [BB * NN * 3];
__device__ float g_fps_locs[BB * SS * 3];
__device__ float g_fps_dim [BB * SS * 3];
__device__ float g_newfeat [BB * SS * HH];   // stage1 output == identity
__device__ float g_h2max   [BB * SS * HH];   // stage2 output

// ---------------- prep: transpose feats, compute dim boxes ----------------
__global__ __launch_bounds__(256) void prep_kernel(
    const float* __restrict__ feats, const float* __restrict__ boxes)
{
    int idx = blockIdx.x * blockDim.x + threadIdx.x;   // over B*N
    if (idx >= BB * NN) return;
    int b = idx >> 17;
    int n = idx & (NN - 1);

    float tmp[CC];
    #pragma unroll
    for (int c = 0; c < CC; c++)
        tmp[c] = feats[(b * CC + c) * NN + n];

    float4* dst = (float4*)(g_feats_nc + ((size_t)idx << 5));
    #pragma unroll
    for (int q = 0; q < 8; q++)
        dst[q] = make_float4(tmp[4*q], tmp[4*q+1], tmp[4*q+2], tmp[4*q+3]);

    const float* bx = boxes + (size_t)idx * 6;
    float* dd = g_dimbox + (size_t)idx * 3;
    dd[0] = bx[3] - bx[0];
    dd[1] = bx[4] - bx[1];
    dd[2] = bx[5] - bx[2];
}

// ---------------- fps gather ----------
__global__ __launch_bounds__(256) void fps_kernel(
    const float* __restrict__ locs, const float* __restrict__ boxes,
    const int* __restrict__ fps_inds, float* __restrict__ out)
{
    int idx = blockIdx.x * blockDim.x + threadIdx.x;   // over B*S
    if (idx >= BB * SS) return;
    int b = idx >> 10;
    int j = fps_inds[idx];

    const float* lp = locs + ((size_t)b * NN + j) * 3;
    float l0 = lp[0], l1 = lp[1], l2 = lp[2];
    g_fps_locs[idx*3+0] = l0; g_fps_locs[idx*3+1] = l1; g_fps_locs[idx*3+2] = l2;
    out[OFF_LOCS + idx*3 + 0] = l0;
    out[OFF_LOCS + idx*3 + 1] = l1;
    out[OFF_LOCS + idx*3 + 2] = l2;

    const float* bx = boxes + ((size_t)b * NN + j) * 6;
    float b0 = bx[0], b1 = bx[1], b2 = bx[2], b3 = bx[3], b4 = bx[4], b5 = bx[5];
    g_fps_dim[idx*3+0] = b3 - b0;
    g_fps_dim[idx*3+1] = b4 - b1;
    g_fps_dim[idx*3+2] = b5 - b2;
    out[OFF_BOXES + idx*6 + 0] = b0;
    out[OFF_BOXES + idx*6 + 1] = b1;
    out[OFF_BOXES + idx*6 + 2] = b2;
    out[OFF_BOXES + idx*6 + 3] = b3;
    out[OFF_BOXES + idx*6 + 4] = b4;
    out[OFF_BOXES + idx*6 + 5] = b5;

    out[OFF_INDS + idx] = (float)j;
}

// ================= stage 1: 4 queries/block, 64 thr/q, 2 chunks of 32 ====
// smem floats: wa[1216] wb[2048] ba[32] bb[64] | per-q: g1[38*32] h1[32*32]
#define S1_BASE (D1*CC + CC*HH + CC + HH)         // 3360
#define S1_PERQ (D1*CH + CC*CH)                   // 2240
#define S1_SMEM ((S1_BASE + 4*S1_PERQ) * 4)       // 49280 bytes

__global__ __launch_bounds__(256, 4) void stage1_kernel(
    const float* __restrict__ locs, const int* __restrict__ nbr,
    const float* __restrict__ w1a, const float* __restrict__ s1a, const float* __restrict__ t1a,
    const float* __restrict__ w1b, const float* __restrict__ s1b, const float* __restrict__ t1b)
{
    extern __shared__ float sm[];
    float* wa_s = sm;                 // D1*CC
    float* wb_s = wa_s + D1*CC;       // CC*HH
    float* ba_s = wb_s + CC*HH;       // CC
    float* bb_s = ba_s + CC;          // HH
    int tid  = threadIdx.x;
    int q    = tid >> 6;              // 0..3
    int ltid = tid & 63;
    float* g1_s = sm + S1_BASE + q * S1_PERQ;   // D1*CH
    float* h1_s = g1_s + D1*CH;                 // CC*CH

    int bs = blockIdx.x * 4 + q;
    int b  = bs >> 10;

    for (int i = tid; i < D1 * CC; i += 256) wa_s[i] = w1a[i] * s1a[i & 31];
    for (int i = tid; i < CC * HH; i += 256) wb_s[i] = w1b[i] * s1b[i & 63];
    if (tid < CC) ba_s[tid] = t1a[tid];
    if (tid < HH) bb_s[tid] = t1b[tid];

    int ngrp = ltid & 7, cgrp = ltid >> 3;   // 8 ngrps x 8 cgrps
    int n0 = ngrp * 4;
    int nb   = ltid & 31;                    // staging: 2 threads per neighbor
    int half = ltid >> 5;

    float qx = g_fps_locs[bs*3+0], qy = g_fps_locs[bs*3+1], qz = g_fps_locs[bs*3+2];
    float qdx = g_fps_dim[bs*3+0], qdy = g_fps_dim[bs*3+1], qdz = g_fps_dim[bs*3+2];

    float m[8];
    #pragma unroll
    for (int cc = 0; cc < 8; cc++) m[cc] = -3.4e38f;

    #pragma unroll 1
    for (int c = 0; c < NCHUNK; c++) {
        // ---- stage chunk c: g1_s[i][n] ----
        {
            int j = nbr[bs * KK + c * CH + nb];
            const float4* fp = (const float4*)(g_feats_nc + (((size_t)b * NN + j) << 5));
            if (half == 0) {
                const float* lp = locs + ((size_t)b * NN + j) * 3;
                g1_s[0*CH + nb] = (lp[0] - qx) * 2.5f;
                g1_s[1*CH + nb] = (lp[1] - qy) * 2.5f;
                g1_s[2*CH + nb] = (lp[2] - qz) * 2.5f;
                const float* dp = g_dimbox + ((size_t)b * NN + j) * 3;
                g1_s[3*CH + nb] = fabsf(dp[0] - qdx);
                g1_s[4*CH + nb] = fabsf(dp[1] - qdy);
                g1_s[5*CH + nb] = fabsf(dp[2] - qdz);
                #pragma unroll
                for (int qq = 0; qq < 4; qq++) {
                    float4 v = fp[qq];
                    g1_s[(6+4*qq+0)*CH + nb] = v.x;
                    g1_s[(6+4*qq+1)*CH + nb] = v.y;
                    g1_s[(6+4*qq+2)*CH + nb] = v.z;
                    g1_s[(6+4*qq+3)*CH + nb] = v.w;
                }
            } else {
                #pragma unroll
                for (int qq = 4; qq < 8; qq++) {
                    float4 v = fp[qq];
                    g1_s[(6+4*qq+0)*CH + nb] = v.x;
                    g1_s[(6+4*qq+1)*CH + nb] = v.y;
                    g1_s[(6+4*qq+2)*CH + nb] = v.z;
                    g1_s[(6+4*qq+3)*CH + nb] = v.w;
                }
            }
        }
        __syncthreads();

        // ---- GEMM A: 38 -> 32, relu. Tile 4n x 4c. ----
        {
            int c0 = cgrp * 4;
            ull acc[4][2];
            ull bi0 = pack2(ba_s[c0+0], ba_s[c0+1]);
            ull bi1 = pack2(ba_s[c0+2], ba_s[c0+3]);
            #pragma unroll
            for (int n = 0; n < 4; n++) { acc[n][0] = bi0; acc[n][1] = bi1; }

            #pragma unroll 2
            for (int i = 0; i < D1; i++) {
                float4 gv = *(const float4*)(g1_s + i * CH + n0);
                ulonglong2 wv = *(const ulonglong2*)(wa_s + i * CC + c0);
                ull gg[4] = { pack2(gv.x,gv.x), pack2(gv.y,gv.y), pack2(gv.z,gv.z), pack2(gv.w,gv.w) };
                #pragma unroll
                for (int n = 0; n < 4; n++) {
                    fma2(acc[n][0], gg[n], wv.x);
                    fma2(acc[n][1], gg[n], wv.y);
                }
            }
            #pragma unroll
            for (int p = 0; p < 2; p++) {
                float lo[4], hi[4];
                #pragma unroll
                for (int n = 0; n < 4; n++) unpack2(acc[n][p], lo[n], hi[n]);
                *(float4*)(h1_s + (c0+2*p+0)*CH + n0) =
                    make_float4(fmaxf(lo[0],0.f), fmaxf(lo[1],0.f), fmaxf(lo[2],0.f), fmaxf(lo[3],0.f));
                *(float4*)(h1_s + (c0+2*p+1)*CH + n0) =
                    make_float4(fmaxf(hi[0],0.f), fmaxf(hi[1],0.f), fmaxf(hi[2],0.f), fmaxf(hi[3],0.f));
            }
        }
        __syncthreads();

        // ---- GEMM B: 32 -> 64, running max. Tile 4n x 8c. ----
        {
            int c0 = cgrp * 8;
            ull acc[4][4];
            #pragma unroll
            for (int p = 0; p < 4; p++) {
                ull bi = pack2(bb_s[c0+2*p], bb_s[c0+2*p+1]);
                #pragma unroll
                for (int n = 0; n < 4; n++) acc[n][p] = bi;
            }
            #pragma unroll 2
            for (int i = 0; i < CC; i++) {
                float4 gv = *(const float4*)(h1_s + i * CH + n0);
                ulonglong2 w0 = *(const ulonglong2*)(wb_s + i * HH + c0);
                ulonglong2 w1 = *(const ulonglong2*)(wb_s + i * HH + c0 + 4);
                ull wc[4] = { w0.x, w0.y, w1.x, w1.y };
                ull gg[4] = { pack2(gv.x,gv.x), pack2(gv.y,gv.y), pack2(gv.z,gv.z), pack2(gv.w,gv.w) };
                #pragma unroll
                for (int n = 0; n < 4; n++)
                    #pragma unroll
                    for (int p = 0; p < 4; p++) fma2(acc[n][p], gg[n], wc[p]);
            }
            #pragma unroll
            for (int p = 0; p < 4; p++)
                #pragma unroll
                for (int n = 0; n < 4; n++) {
                    float lo, hi; unpack2(acc[n][p], lo, hi);
                    m[2*p]   = fmaxf(m[2*p], lo);
                    m[2*p+1] = fmaxf(m[2*p+1], hi);
                }
        }
        __syncthreads();   // protect g1_s/h1_s before next chunk staging
    }

    // warp reduce over 8 ngrps (lane bits 0..2), then relu + store
    #pragma unroll
    for (int cc = 0; cc < 8; cc++) {
        m[cc] = fmaxf(m[cc], __shfl_xor_sync(0xffffffffu, m[cc], 1));
        m[cc] = fmaxf(m[cc], __shfl_xor_sync(0xffffffffu, m[cc], 2));
        m[cc] = fmaxf(m[cc], __shfl_xor_sync(0xffffffffu, m[cc], 4));
    }
    if (ngrp == 0) {
        int c0 = cgrp * 8;
        float4 v0 = make_float4(fmaxf(m[0],0.f), fmaxf(m[1],0.f), fmaxf(m[2],0.f), fmaxf(m[3],0.f));
        float4 v1 = make_float4(fmaxf(m[4],0.f), fmaxf(m[5],0.f), fmaxf(m[6],0.f), fmaxf(m[7],0.f));
        *(float4*)(g_newfeat + bs * HH + c0)     = v0;
        *(float4*)(g_newfeat + bs * HH + c0 + 4) = v1;
    }
}

// ================= stage 2: 4 queries/block, 64 thr/q, 2 chunks of 32 ====
// smem floats: w[4480] sb[64] | per-q: g[70*32]
#define S2_BASE (D2*HH + HH)                      // 4544
#define S2_PERQ (D2*CH)                           // 2240
#define S2_SMEM ((S2_BASE + 4*S2_PERQ) * 4)       // 54016 bytes

__global__ __launch_bounds__(256, 4) void stage2_kernel(
    const int* __restrict__ nbr2,
    const float* __restrict__ w2, const float* __restrict__ s2, const float* __restrict__ t2)
{
    extern __shared__ float sm[];
    float* w_s = sm;                  // D2*HH
    float* sb  = w_s + D2*HH;         // HH
    int tid  = threadIdx.x;
    int q    = tid >> 6;
    int ltid = tid & 63;
    float* g_s = sm + S2_BASE + q * S2_PERQ;   // D2*CH

    int bs = blockIdx.x * 4 + q;
    int b  = bs >> 10;

    for (int i = tid; i < D2 * HH; i += 256) w_s[i] = w2[i] * s2[i & 63];
    if (tid < HH) sb[tid] = t2[tid];

    int ngrp = ltid & 7, cgrp = ltid >> 3;
    int n0 = ngrp * 4, c0 = cgrp * 8;
    int nb   = ltid & 31;
    int half = ltid >> 5;

    float qx = g_fps_locs[bs*3+0], qy = g_fps_locs[bs*3+1], qz = g_fps_locs[bs*3+2];
    float qdx = g_fps_dim[bs*3+0], qdy = g_fps_dim[bs*3+1], qdz = g_fps_dim[bs*3+2];

    float m[8];
    #pragma unroll
    for (int cc = 0; cc < 8; cc++) m[cc] = -3.4e38f;

    #pragma unroll 1
    for (int c = 0; c < NCHUNK; c++) {
        // ---- stage chunk c ----
        {
            int j  = nbr2[bs * KK + c * CH + nb];
            int fj = (b << 10) + j;
            const float4* fp = (const float4*)(g_newfeat + (size_t)fj * HH);
            if (half == 0) {
                g_s[0*CH + nb] = (g_fps_locs[fj*3+0] - qx) * 1.25f;
                g_s[1*CH + nb] = (g_fps_locs[fj*3+1] - qy) * 1.25f;
                g_s[2*CH + nb] = (g_fps_locs[fj*3+2] - qz) * 1.25f;
                g_s[3*CH + nb] = fabsf(g_fps_dim[fj*3+0] - qdx);
                g_s[4*CH + nb] = fabsf(g_fps_dim[fj*3+1] - qdy);
                g_s[5*CH + nb] = fabsf(g_fps_dim[fj*3+2] - qdz);
                #pragma unroll
                for (int qq = 0; qq < 8; qq++) {
                    float4 v = fp[qq];
                    g_s[(6+4*qq+0)*CH + nb] = v.x;
                    g_s[(6+4*qq+1)*CH + nb] = v.y;
                    g_s[(6+4*qq+2)*CH + nb] = v.z;
                    g_s[(6+4*qq+3)*CH + nb] = v.w;
                }
            } else {
                #pragma unroll
                for (int qq = 8; qq < 16; qq++) {
                    float4 v = fp[qq];
                    g_s[(6+4*qq+0)*CH + nb] = v.x;
                    g_s[(6+4*qq+1)*CH + nb] = v.y;
                    g_s[(6+4*qq+2)*CH + nb] = v.z;
                    g_s[(6+4*qq+3)*CH + nb] = v.w;
                }
            }
        }
        __syncthreads();

        // ---- GEMM: 70 -> 64, running max. Tile 4n x 8c. ----
        {
            ull acc[4][4];
            #pragma unroll
            for (int p = 0; p < 4; p++) {
                ull bi = pack2(sb[c0+2*p], sb[c0+2*p+1]);
                #pragma unroll
                for (int n = 0; n < 4; n++) acc[n][p] = bi;
            }
            #pragma unroll 2
            for (int i = 0; i < D2; i++) {
                float4 gv = *(const float4*)(g_s + i * CH + n0);
                ulonglong2 w0 = *(const ulonglong2*)(w_s + i * HH + c0);
                ulonglong2 w1 = *(const ulonglong2*)(w_s + i * HH + c0 + 4);
                ull wc[4] = { w0.x, w0.y, w1.x, w1.y };
                ull gg[4] = { pack2(gv.x,gv.x), pack2(gv.y,gv.y), pack2(gv.z,gv.z), pack2(gv.w,gv.w) };
                #pragma unroll
                for (int n = 0; n < 4; n++)
                    #pragma unroll
                    for (int p = 0; p < 4; p++) fma2(acc[n][p], gg[n], wc[p]);
            }
            #pragma unroll
            for (int p = 0; p < 4; p++)
                #pragma unroll
                for (int n = 0; n < 4; n++) {
                    float lo, hi; unpack2(acc[n][p], lo, hi);
                    m[2*p]   = fmaxf(m[2*p], lo);
                    m[2*p+1] = fmaxf(m[2*p+1], hi);
                }
        }
        __syncthreads();
    }

    #pragma unroll
    for (int cc = 0; cc < 8; cc++) {
        m[cc] = fmaxf(m[cc], __shfl_xor_sync(0xffffffffu, m[cc], 1));
        m[cc] = fmaxf(m[cc], __shfl_xor_sync(0xffffffffu, m[cc], 2));
        m[cc] = fmaxf(m[cc], __shfl_xor_sync(0xffffffffu, m[cc], 4));
    }
    if (ngrp == 0) {
        *(float4*)(g_h2max + bs * HH + c0)     = make_float4(m[0], m[1], m[2], m[3]);
        *(float4*)(g_h2max + bs * HH + c0 + 4) = make_float4(m[4], m[5], m[6], m[7]);
    }
}

// ---------------- stage 3: bottleneck mlp3 + skip, write transposed ------
#define TS 16
__global__ __launch_bounds__(256) void stage3_kernel(
    const float* __restrict__ w3a, const float* __restrict__ s3a, const float* __restrict__ t3a,
    const float* __restrict__ w3b, const float* __restrict__ s3b, const float* __restrict__ t3b,
    float* __restrict__ out)
{
    __shared__ float h2s[TS * HH];
    __shared__ float h3s[TS * H3];
    int t = threadIdx.x;
    int row0 = blockIdx.x * TS;

    for (int i = t; i < TS * HH; i += 256) h2s[i] = g_h2max[row0 * HH + i];
    __syncthreads();

    {
        float sc = s3a[t], bi = t3a[t];
        float acc[TS];
        #pragma unroll
        for (int r = 0; r < TS; r++) acc[r] = bi;
        #pragma unroll 4
        for (int i = 0; i < HH; i++) {
            float wv = w3a[i * H3 + t] * sc;
            #pragma unroll
            for (int r = 0; r < TS; r++) acc[r] += h2s[r * HH + i] * wv;
        }
        #pragma unroll
        for (int r = 0; r < TS; r++) h3s[r * H3 + t] = fmaxf(acc[r], 0.0f);
    }
    __syncthreads();

    {
        int c  = t & 63;
        int rg = t >> 6;
        float sc = s3b[c], bi = t3b[c];
        float acc[4];
        #pragma unroll
        for (int rr = 0; rr < 4; rr++) acc[rr] = bi;
        #pragma unroll 4
        for (int i = 0; i < H3; i++) {
            float wv = w3b[i * HH + c] * sc;
            #pragma unroll
            for (int rr = 0; rr < 4; rr++)
                acc[rr] += h3s[(rg * 4 + rr) * H3 + i] * wv;
        }
        #pragma unroll
        for (int rr = 0; rr < 4; rr++) {
            int row = row0 + rg * 4 + rr;
            int b = row >> 10, s = row & 1023;
            float v = acc[rr] + g_newfeat[row * HH + c];
            out[OFF_OUT + ((b * HH + c) << 10) + s] = fmaxf(v, 0.0f);
        }
    }
}

// ---------------- launch ----------------
extern "C" void kernel_launch(void* const* d_in, const int* in_sizes, int n_in,
                              void* d_out, int out_size)
{
    const float* locs  = (const float*)d_in[0];
    const float* feats = (const float*)d_in[1];
    const float* boxes = (const float*)d_in[2];
    const int*   fps   = (const int*)d_in[3];
    const int*   nbr   = (const int*)d_in[4];
    const int*   nbr2  = (const int*)d_in[5];
    const float* w1a = (const float*)d_in[6];
    const float* s1a = (const float*)d_in[7];
    const float* t1a = (const float*)d_in[8];
    const float* w1b = (const float*)d_in[9];
    const float* s1b = (const float*)d_in[10];
    const float* t1b = (const float*)d_in[11];
    const float* w2  = (const float*)d_in[12];
    const float* s2  = (const float*)d_in[13];
    const float* t2  = (const float*)d_in[14];
    const float* w3a = (const float*)d_in[15];
    const float* s3a = (const float*)d_in[16];
    const float* t3a = (const float*)d_in[17];
    const float* w3b = (const float*)d_in[18];
    const float* s3b = (const float*)d_in[19];
    const float* t3b = (const float*)d_in[20];
    float* out = (float*)d_out;

    cudaFuncSetAttribute(stage1_kernel, cudaFuncAttributeMaxDynamicSharedMemorySize, S1_SMEM);
    cudaFuncSetAttribute(stage2_kernel, cudaFuncAttributeMaxDynamicSharedMemorySize, S2_SMEM);

    prep_kernel<<<(BB * NN + 255) / 256, 256>>>(feats, boxes);
    fps_kernel<<<(BB * SS + 255) / 256, 256>>>(locs, boxes, fps, out);
    stage1_kernel<<<BB * SS / 4, 256, S1_SMEM>>>(locs, nbr, w1a, s1a, t1a, w1b, s1b, t1b);
    stage2_kernel<<<BB * SS / 4, 256, S2_SMEM>>>(nbr2, w2, s2, t2);
    stage3_kernel<<<(BB * SS) / TS, 256>>>(w3a, s3a, t3a, w3b, s3b, t3b, out);
}